// round 3
// baseline (speedup 1.0000x reference)
#include <cuda_runtime.h>

// CBOW hierarchical softmax loss, fused single-block kernel.
// Inputs (metadata order):
//   d_in[0] context_idx  int32[10]
//   d_in[1] path_indices int32[17]
//   d_in[2] code_bits    int32[17]
//   d_in[3] ctx_emb      float32[100000*512]
//   d_in[4] node_emb     float32[200000*512]
// Output: float32[1] = loss

#define EMBED   512
#define WINDOW  10
#define PATHLEN 17
#define EPS     1e-9f

__global__ __launch_bounds__(EMBED, 1)
void cbow_hs_kernel(const int* __restrict__ ctx_idx,
                    const int* __restrict__ path_idx,
                    const int* __restrict__ code_bits,
                    const float* __restrict__ ctx_emb,
                    const float* __restrict__ node_emb,
                    float* __restrict__ out)
{
    __shared__ float h_s[EMBED];
    __shared__ float terms[32];     // 17 used, one slot per path

    const int tid  = threadIdx.x;
    const int wid  = tid >> 5;      // 0..15
    const int lane = tid & 31;

    // Warp wid owns path wid; warp 0 additionally owns path 16.
    const int npaths = (wid == 0) ? 2 : 1;

    // ---- Phase A: front-load ALL gathers so node-row and ctx-row DRAM
    // latencies overlap (one exposed round-trip instead of two). Also
    // front-load code bits so they're not a dependent load in the tail. ----
    float4 nv[8];
    int    cb[2];
    #pragma unroll
    for (int j = 0; j < 2; j++) {
        if (j < npaths) {
            const int p = (j == 0) ? wid : 16;
            cb[j] = __ldg(&code_bits[p]);
            const long base = (long)__ldg(&path_idx[p]) * EMBED;
            const float4* row = (const float4*)(node_emb + base);
            #pragma unroll
            for (int i = 0; i < 4; i++)
                nv[j * 4 + i] = __ldg(&row[lane + 32 * i]);
        }
    }

    // h: thread `tid` owns dimension `tid`; 10 independent coalesced loads.
    float hv = 0.0f;
    #pragma unroll
    for (int w = 0; w < WINDOW; w++) {
        const long base = (long)__ldg(&ctx_idx[w]) * EMBED;
        hv += __ldg(&ctx_emb[base + tid]);
    }
    h_s[tid] = hv * (1.0f / WINDOW);
    __syncthreads();

    // ---- Phase B: dot products from registers x smem, warp reduce,
    // per-path loss term -> smem slot (NO shared atomics). ----
    const float4* h4 = (const float4*)h_s;
    #pragma unroll
    for (int j = 0; j < 2; j++) {
        if (j < npaths) {
            const int p = (j == 0) ? wid : 16;
            float dot = 0.0f;
            #pragma unroll
            for (int i = 0; i < 4; i++) {
                const float4 hh = h4[lane + 32 * i];
                const float4 n  = nv[j * 4 + i];
                dot += n.x * hh.x + n.y * hh.y + n.z * hh.z + n.w * hh.w;
            }
            #pragma unroll
            for (int off = 16; off; off >>= 1)
                dot += __shfl_xor_sync(0xffffffffu, dot, off);
            if (lane == 0) {
                // fast-math sigmoid + log: MUFU-based, rel err ~1e-6 << 1e-3 budget
                const float s = __fdividef(1.0f, 1.0f + __expf(-dot));
                const float prob = (cb[j] == 1) ? s : (1.0f - s);
                terms[p] = -__logf(prob + EPS);
            }
        }
    }
    __syncthreads();

    // ---- Phase C: warp 0 reduces the 17 loss terms and writes out. ----
    if (wid == 0) {
        float t = (lane < PATHLEN) ? terms[lane] : 0.0f;
        #pragma unroll
        for (int off = 16; off; off >>= 1)
            t += __shfl_xor_sync(0xffffffffu, t, off);
        if (lane == 0) out[0] = t;
    }
}

extern "C" void kernel_launch(void* const* d_in, const int* in_sizes, int n_in,
                              void* d_out, int out_size)
{
    const int*   ctx_idx   = (const int*)d_in[0];
    const int*   path_idx  = (const int*)d_in[1];
    const int*   code_bits = (const int*)d_in[2];
    const float* ctx_emb   = (const float*)d_in[3];
    const float* node_emb  = (const float*)d_in[4];
    float*       out       = (float*)d_out;

    cbow_hs_kernel<<<1, EMBED>>>(ctx_idx, path_idx, code_bits,
                                 ctx_emb, node_emb, out);
}

// round 5
// speedup vs baseline: 1.2917x; 1.2917x over previous
#include <cuda_runtime.h>

// CBOW hierarchical softmax loss, fused single-block kernel.
// Inputs (metadata order):
//   d_in[0] context_idx  int32[10]
//   d_in[1] path_indices int32[17]
//   d_in[2] code_bits    int32[17]
//   d_in[3] ctx_emb      float32[100000*512]
//   d_in[4] node_emb     float32[200000*512]
// Output: float32[1] = loss

#define EMBED   512
#define WINDOW  10
#define PATHLEN 17
#define EPS     1e-9f
#define NTHREADS (PATHLEN * 32)   // 544: one warp per path

__device__ __forceinline__ float warp_sum(float v) {
    #pragma unroll
    for (int off = 16; off; off >>= 1)
        v += __shfl_xor_sync(0xffffffffu, v, off);
    return v;
}

__global__ __launch_bounds__(NTHREADS, 1)
void cbow_hs_kernel(const int* __restrict__ ctx_idx,
                    const int* __restrict__ path_idx,
                    const int* __restrict__ code_bits,
                    const float* __restrict__ ctx_emb,
                    const float* __restrict__ node_emb,
                    float* __restrict__ out)
{
    __shared__ float h_s[EMBED];
    __shared__ float terms[32];     // 17 used

    const int tid  = threadIdx.x;
    const int wid  = tid >> 5;      // 0..16 == path id
    const int lane = tid & 31;

    // ---- Issue ALL index loads first (vectorized), then all row gathers,
    // so the two dependent DRAM/L2 round-trips stay fully overlapped. ----
    const int  pi = __ldg(&path_idx[wid]);
    const int  cb = __ldg(&code_bits[wid]);
    const int4 c0 = __ldg((const int4*)ctx_idx);        // ctx_idx[0..3]
    const int4 c1 = __ldg((const int4*)ctx_idx + 1);    // ctx_idx[4..7]
    const int2 c2 = __ldg((const int2*)(ctx_idx + 8));  // ctx_idx[8..9]

    // Node row for this warp's path: 512 floats = 4 x float4 per lane.
    const float4* nrow = (const float4*)(node_emb + (long)pi * EMBED);
    float4 nv[4];
    #pragma unroll
    for (int i = 0; i < 4; i++)
        nv[i] = __ldg(&nrow[lane + 32 * i]);

    // h: thread tid owns dim tid (tid < 512); 10 independent coalesced loads.
    if (tid < EMBED) {
        float hv;
        hv  = __ldg(&ctx_emb[(long)c0.x * EMBED + tid]);
        hv += __ldg(&ctx_emb[(long)c0.y * EMBED + tid]);
        hv += __ldg(&ctx_emb[(long)c0.z * EMBED + tid]);
        hv += __ldg(&ctx_emb[(long)c0.w * EMBED + tid]);
        hv += __ldg(&ctx_emb[(long)c1.x * EMBED + tid]);
        hv += __ldg(&ctx_emb[(long)c1.y * EMBED + tid]);
        hv += __ldg(&ctx_emb[(long)c1.z * EMBED + tid]);
        hv += __ldg(&ctx_emb[(long)c1.w * EMBED + tid]);
        hv += __ldg(&ctx_emb[(long)c2.x * EMBED + tid]);
        hv += __ldg(&ctx_emb[(long)c2.y * EMBED + tid]);
        h_s[tid] = hv;              // raw sum; /WINDOW folded into dot below
    }
    __syncthreads();

    // ---- Dot: registers x smem; 4 independent partial chains to shorten
    // the FFMA dependency depth, then pairwise combine + shuffle tree. ----
    const float4* h4 = (const float4*)h_s;
    float d0 = 0.f, d1 = 0.f, d2 = 0.f, d3 = 0.f;
    {
        float4 hh;
        hh = h4[lane];       d0 = nv[0].x*hh.x + nv[0].y*hh.y + nv[0].z*hh.z + nv[0].w*hh.w;
        hh = h4[lane + 32];  d1 = nv[1].x*hh.x + nv[1].y*hh.y + nv[1].z*hh.z + nv[1].w*hh.w;
        hh = h4[lane + 64];  d2 = nv[2].x*hh.x + nv[2].y*hh.y + nv[2].z*hh.z + nv[2].w*hh.w;
        hh = h4[lane + 96];  d3 = nv[3].x*hh.x + nv[3].y*hh.y + nv[3].z*hh.z + nv[3].w*hh.w;
    }
    float dot = warp_sum((d0 + d1) + (d2 + d3)) * (1.0f / WINDOW);

    // Branch-free loss term on all lanes (no BSSY/BSYNC around MUFU):
    // prob = sigmoid(x) if bit==1 else sigmoid(-x); term = -log(prob + EPS)
    const float sx   = (cb == 1) ? -dot : dot;
    const float prob = __fdividef(1.0f, 1.0f + __expf(sx));
    const float term = -__logf(prob + EPS);
    if (lane == 0) terms[wid] = term;
    __syncthreads();

    // ---- Final: warp 0 reduces 17 terms, one STG. ----
    if (wid == 0) {
        float t = (lane < PATHLEN) ? terms[lane] : 0.0f;
        t = warp_sum(t);
        if (lane == 0) out[0] = t;
    }
}

extern "C" void kernel_launch(void* const* d_in, const int* in_sizes, int n_in,
                              void* d_out, int out_size)
{
    const int*   ctx_idx   = (const int*)d_in[0];
    const int*   path_idx  = (const int*)d_in[1];
    const int*   code_bits = (const int*)d_in[2];
    const float* ctx_emb   = (const float*)d_in[3];
    const float* node_emb  = (const float*)d_in[4];
    float*       out       = (float*)d_out;

    cbow_hs_kernel<<<1, NTHREADS>>>(ctx_idx, path_idx, code_bits,
                                    ctx_emb, node_emb, out);
}

// round 6
// speedup vs baseline: 1.3413x; 1.0385x over previous
#include <cuda_runtime.h>

// CBOW hierarchical softmax loss, fused single-block kernel.
// Inputs (metadata order):
//   d_in[0] context_idx  int32[10]
//   d_in[1] path_indices int32[17]
//   d_in[2] code_bits    int32[17]
//   d_in[3] ctx_emb      float32[100000*512]
//   d_in[4] node_emb     float32[200000*512]
// Output: float32[1] = loss

#define EMBED   512
#define WINDOW  10
#define PATHLEN 17
#define EPS     1e-9f
#define NTHREADS (PATHLEN * 32)   // 544: one warp per path

__device__ __forceinline__ float warp_sum(float v) {
    #pragma unroll
    for (int off = 16; off; off >>= 1)
        v += __shfl_xor_sync(0xffffffffu, v, off);
    return v;
}

__global__ __launch_bounds__(NTHREADS, 1)
void cbow_hs_kernel(const int* __restrict__ ctx_idx,
                    const int* __restrict__ path_idx,
                    const int* __restrict__ code_bits,
                    const float* __restrict__ ctx_emb,
                    const float* __restrict__ node_emb,
                    float* __restrict__ out)
{
    __shared__ float h_s[EMBED];
    __shared__ float terms[32];     // 17 used

    const int tid  = threadIdx.x;
    const int wid  = tid >> 5;      // 0..16 == path id
    const int lane = tid & 31;

    // ---- Issue ALL index loads first (vectorized), then all row gathers,
    // so the two dependent L2/DRAM round-trips stay fully overlapped. ----
    const int  pi = __ldg(&path_idx[wid]);
    const int  cb = __ldg(&code_bits[wid]);

    // Node row for this warp's path: 512 floats = 4 x float4 per lane.
    const float4* nrow = (const float4*)(node_emb + (long)pi * EMBED);
    float4 nv[4];
    #pragma unroll
    for (int i = 0; i < 4; i++)
        nv[i] = __ldg(&nrow[lane + 32 * i]);

    // h: 128 threads x float4 -> 10 LDG.128 each (40 warp-instructions total
    // instead of 160 scalar ones). Thread t owns dims [4t, 4t+4).
    if (tid < EMBED / 4) {
        const int4 c0 = __ldg((const int4*)ctx_idx);        // ctx_idx[0..3]
        const int4 c1 = __ldg((const int4*)ctx_idx + 1);    // ctx_idx[4..7]
        const int2 c2 = __ldg((const int2*)(ctx_idx + 8));  // ctx_idx[8..9]
        const float4* ce = (const float4*)ctx_emb;
        const int     q  = EMBED / 4;                       // 128 float4 per row

        float4 v0 = __ldg(&ce[(long)c0.x * q + tid]);
        float4 v1 = __ldg(&ce[(long)c0.y * q + tid]);
        float4 v2 = __ldg(&ce[(long)c0.z * q + tid]);
        float4 v3 = __ldg(&ce[(long)c0.w * q + tid]);
        float4 v4 = __ldg(&ce[(long)c1.x * q + tid]);
        float4 v5 = __ldg(&ce[(long)c1.y * q + tid]);
        float4 v6 = __ldg(&ce[(long)c1.z * q + tid]);
        float4 v7 = __ldg(&ce[(long)c1.w * q + tid]);
        float4 v8 = __ldg(&ce[(long)c2.x * q + tid]);
        float4 v9 = __ldg(&ce[(long)c2.y * q + tid]);

        float4 hv;      // pairwise tree add, short dependency depth
        hv.x = ((v0.x + v1.x) + (v2.x + v3.x)) + ((v4.x + v5.x) + (v6.x + v7.x)) + (v8.x + v9.x);
        hv.y = ((v0.y + v1.y) + (v2.y + v3.y)) + ((v4.y + v5.y) + (v6.y + v7.y)) + (v8.y + v9.y);
        hv.z = ((v0.z + v1.z) + (v2.z + v3.z)) + ((v4.z + v5.z) + (v6.z + v7.z)) + (v8.z + v9.z);
        hv.w = ((v0.w + v1.w) + (v2.w + v3.w)) + ((v4.w + v5.w) + (v6.w + v7.w)) + (v8.w + v9.w);
        ((float4*)h_s)[tid] = hv;   // raw sum; /WINDOW folded into dot below
    }
    __syncthreads();

    // ---- Dot: registers x smem; 4 independent partial chains, pairwise
    // combine, then the shuffle tree. ----
    const float4* h4 = (const float4*)h_s;
    float d0, d1, d2, d3;
    {
        float4 hh;
        hh = h4[lane];       d0 = nv[0].x*hh.x + nv[0].y*hh.y + nv[0].z*hh.z + nv[0].w*hh.w;
        hh = h4[lane + 32];  d1 = nv[1].x*hh.x + nv[1].y*hh.y + nv[1].z*hh.z + nv[1].w*hh.w;
        hh = h4[lane + 64];  d2 = nv[2].x*hh.x + nv[2].y*hh.y + nv[2].z*hh.z + nv[2].w*hh.w;
        hh = h4[lane + 96];  d3 = nv[3].x*hh.x + nv[3].y*hh.y + nv[3].z*hh.z + nv[3].w*hh.w;
    }
    float dot = warp_sum((d0 + d1) + (d2 + d3)) * (1.0f / WINDOW);

    // Branch-free loss term on all lanes:
    // prob = sigmoid(dot) if bit==1 else 1-sigmoid(dot); term = -log(prob+EPS)
    const float sx   = (cb == 1) ? -dot : dot;
    const float prob = __fdividef(1.0f, 1.0f + __expf(sx));
    const float term = -__logf(prob + EPS);
    if (lane == 0) terms[wid] = term;

    // ---- Split barrier: producers arrive (non-blocking) and exit; warp 0
    // blocks, reduces the 17 terms, and writes out. ----
    if (wid != 0) {
        asm volatile("bar.arrive 1, %0;" :: "r"(NTHREADS) : "memory");
    } else {
        asm volatile("bar.sync 1, %0;" :: "r"(NTHREADS) : "memory");
        float t = (lane < PATHLEN) ? terms[lane] : 0.0f;
        t = warp_sum(t);
        if (lane == 0) out[0] = t;
    }
}

extern "C" void kernel_launch(void* const* d_in, const int* in_sizes, int n_in,
                              void* d_out, int out_size)
{
    const int*   ctx_idx   = (const int*)d_in[0];
    const int*   path_idx  = (const int*)d_in[1];
    const int*   code_bits = (const int*)d_in[2];
    const float* ctx_emb   = (const float*)d_in[3];
    const float* node_emb  = (const float*)d_in[4];
    float*       out       = (float*)d_out;

    cbow_hs_kernel<<<1, NTHREADS>>>(ctx_idx, path_idx, code_bits,
                                    ctx_emb, node_emb, out);
}

// round 8
// speedup vs baseline: 1.4381x; 1.0722x over previous
#include <cuda_runtime.h>

// CBOW hierarchical softmax loss, fused single-block kernel.
// Inputs (metadata order):
//   d_in[0] context_idx  int32[10]
//   d_in[1] path_indices int32[17]
//   d_in[2] code_bits    int32[17]
//   d_in[3] ctx_emb      float32[100000*512]
//   d_in[4] node_emb     float32[200000*512]
// Output: float32[1] = loss

#define EMBED   512
#define WINDOW  10
#define PATHLEN 17
#define EPS     1e-9f
#define NTHREADS (PATHLEN * 32)   // 544: one warp per path

__device__ __forceinline__ float warp_sum(float v) {
    #pragma unroll
    for (int off = 16; off; off >>= 1)
        v += __shfl_xor_sync(0xffffffffu, v, off);
    return v;
}

__global__ __launch_bounds__(NTHREADS, 1)
void cbow_hs_kernel(const int* __restrict__ ctx_idx,
                    const int* __restrict__ path_idx,
                    const int* __restrict__ code_bits,
                    const float* __restrict__ ctx_emb,
                    const float* __restrict__ node_emb,
                    float* __restrict__ out)
{
    __shared__ float h_s[EMBED];
    __shared__ float terms[32];     // 17 used (slot 0 unused by the reduce)

    const int tid  = threadIdx.x;
    const int wid  = tid >> 5;      // 0..16 == path id
    const int lane = tid & 31;

    // ---- Issue ALL index loads first, then all row gathers, so the two
    // dependent L2/DRAM round-trips stay fully overlapped. ----
    const int  pi = __ldg(&path_idx[wid]);
    const int  cb = __ldg(&code_bits[wid]);

    // Node row for this warp's path: 512 floats = 4 x float4 per lane.
    const float4* nrow = (const float4*)(node_emb + (long)pi * EMBED);
    float4 nv[4];
    #pragma unroll
    for (int i = 0; i < 4; i++)
        nv[i] = __ldg(&nrow[lane + 32 * i]);

    // h: 128 threads x float4 -> 10 LDG.128 each (40 warp-instructions).
    // Thread t owns dims [4t, 4t+4). 1/WINDOW folded in here, off the
    // post-shuffle critical path.
    if (tid < EMBED / 4) {
        const int4 c0 = __ldg((const int4*)ctx_idx);        // ctx_idx[0..3]
        const int4 c1 = __ldg((const int4*)ctx_idx + 1);    // ctx_idx[4..7]
        const int2 c2 = __ldg((const int2*)(ctx_idx + 8));  // ctx_idx[8..9]
        const float4* ce = (const float4*)ctx_emb;
        const int     q  = EMBED / 4;                       // 128 float4 per row

        float4 v0 = __ldg(&ce[(long)c0.x * q + tid]);
        float4 v1 = __ldg(&ce[(long)c0.y * q + tid]);
        float4 v2 = __ldg(&ce[(long)c0.z * q + tid]);
        float4 v3 = __ldg(&ce[(long)c0.w * q + tid]);
        float4 v4 = __ldg(&ce[(long)c1.x * q + tid]);
        float4 v5 = __ldg(&ce[(long)c1.y * q + tid]);
        float4 v6 = __ldg(&ce[(long)c1.z * q + tid]);
        float4 v7 = __ldg(&ce[(long)c1.w * q + tid]);
        float4 v8 = __ldg(&ce[(long)c2.x * q + tid]);
        float4 v9 = __ldg(&ce[(long)c2.y * q + tid]);

        const float inv = 1.0f / WINDOW;
        float4 hv;      // pairwise tree add, short dependency depth
        hv.x = (((v0.x + v1.x) + (v2.x + v3.x)) + ((v4.x + v5.x) + (v6.x + v7.x)) + (v8.x + v9.x)) * inv;
        hv.y = (((v0.y + v1.y) + (v2.y + v3.y)) + ((v4.y + v5.y) + (v6.y + v7.y)) + (v8.y + v9.y)) * inv;
        hv.z = (((v0.z + v1.z) + (v2.z + v3.z)) + ((v4.z + v5.z) + (v6.z + v7.z)) + (v8.z + v9.z)) * inv;
        hv.w = (((v0.w + v1.w) + (v2.w + v3.w)) + ((v4.w + v5.w) + (v6.w + v7.w)) + (v8.w + v9.w)) * inv;
        ((float4*)h_s)[tid] = hv;
    }
    __syncthreads();

    // ---- Dot: registers x smem; 4 independent partial chains, pairwise
    // combine, then the shuffle tree. ----
    const float4* h4 = (const float4*)h_s;
    float d0, d1, d2, d3;
    {
        float4 hh;
        hh = h4[lane];       d0 = nv[0].x*hh.x + nv[0].y*hh.y + nv[0].z*hh.z + nv[0].w*hh.w;
        hh = h4[lane + 32];  d1 = nv[1].x*hh.x + nv[1].y*hh.y + nv[1].z*hh.z + nv[1].w*hh.w;
        hh = h4[lane + 64];  d2 = nv[2].x*hh.x + nv[2].y*hh.y + nv[2].z*hh.z + nv[2].w*hh.w;
        hh = h4[lane + 96];  d3 = nv[3].x*hh.x + nv[3].y*hh.y + nv[3].z*hh.z + nv[3].w*hh.w;
    }
    const float dot = warp_sum((d0 + d1) + (d2 + d3));

    // Branch-free loss term on all lanes:
    // prob = sigmoid(dot) if bit==1 else 1-sigmoid(dot); term = -log(prob+EPS)
    const float sx   = (cb == 1) ? -dot : dot;
    const float prob = __fdividef(1.0f, 1.0f + __expf(sx));
    const float term = -__logf(prob + EPS);

    if (wid != 0) {
        // Producers: publish term, arrive (non-blocking), done.
        if (lane == 0) terms[wid] = term;
        asm volatile("bar.arrive 1, %0;" :: "r"(NTHREADS) : "memory");
    } else {
        // Warp 0: keep own term in-register; wait for the other 16, reduce.
        asm volatile("bar.sync 1, %0;" :: "r"(NTHREADS) : "memory");
        float t = (lane > 0 && lane < PATHLEN) ? terms[lane] : 0.0f;
        if (lane == 0) t = term;
        t = warp_sum(t);
        if (lane == 0) out[0] = t;
    }
}

extern "C" void kernel_launch(void* const* d_in, const int* in_sizes, int n_in,
                              void* d_out, int out_size)
{
    const int*   ctx_idx   = (const int*)d_in[0];
    const int*   path_idx  = (const int*)d_in[1];
    const int*   code_bits = (const int*)d_in[2];
    const float* ctx_emb   = (const float*)d_in[3];
    const float* node_emb  = (const float*)d_in[4];
    float*       out       = (float*)d_out;

    cbow_hs_kernel<<<1, NTHREADS>>>(ctx_idx, path_idx, code_bits,
                                    ctx_emb, node_emb, out);
}